// round 6
// baseline (speedup 1.0000x reference)
#include <cuda_runtime.h>
#include <math.h>

// Problem constants
#define Bsz   4
#define Csz   16
#define Tsz   32
#define Hsz   128
#define Wsz   128
#define Klow  4
#define TAU   0.1
#define EPS2  1e-12f          // (1e-6)^2

#define HW        (Hsz * Wsz)          // 16384
#define HW4       (HW / 4)             // 4096
#define NCOLS     (Bsz * Csz * HW4)    // 262,144 16B-columns
#define BLOCK     256
#define NBLOCKS   512                  // one wave at 4 blocks/SM on 148 SMs
#define NTHREADS  (NBLOCKS * BLOCK)    // 131,072 -> 2 columns per thread
#define COLS_PER_THREAD 2

#define N_MAIN  ((double)Bsz * Csz * Tsz * HW)          // 33,554,432
#define N_TEMP  ((double)Bsz * Csz * (Tsz - 1) * HW)    // 32,505,856

__device__ float g_partials[2 * NBLOCKS];
__device__ unsigned int g_count = 0;   // last block resets -> graph-replay safe

// Single-MUFU sqrt (harness has no -use_fast_math; sqrtf would emit ~15-instr
// correctly-rounded emulation).
__device__ __forceinline__ float sqrt_approx(float x) {
    float r;
    asm("sqrt.approx.f32 %0, %1;" : "=f"(r) : "f"(x));
    return r;
}

__global__ void __launch_bounds__(BLOCK, 4)
loss_fused(const float4* __restrict__ X, const float4* __restrict__ Y,
           float* __restrict__ out)
{
    __shared__ float  sD[Klow][Tsz];    // orthonormal DCT rows (for building G)
    __shared__ float4 sWT[Tsz];         // per-t packed weights {w0,w1,w2,w3}
    __shared__ float  sG[Klow * Klow];  // G = E E^T
    __shared__ float  red[2][BLOCK];
    __shared__ bool   is_last;

    const int tid = threadIdx.x;

    // Build D (4x32): one thread per t; pack into float4 per t.
    if (tid < Tsz) {
        const float s  = sqrtf(2.0f / (float)Tsz);   // setup only
        const float ph = (float)M_PI * (2.0f * tid + 1.0f) / (2.0f * (float)Tsz);
        float w0 = s * 0.7071067811865476f;
        float w1 = s * cosf(ph);
        float w2 = s * cosf(2.0f * ph);
        float w3 = s * cosf(3.0f * ph);
        sD[0][tid] = w0; sD[1][tid] = w1; sD[2][tid] = w2; sD[3][tid] = w3;
        sWT[tid] = make_float4(w0, w1, w2, w3);
    }
    __syncthreads();
    if (tid < Klow * Klow) {
        int n = tid >> 2, m = tid & 3;
        float g = 0.0f;
        #pragma unroll
        for (int s = 0; s < Tsz - 1; s++)
            g += (sD[n][s + 1] - sD[n][s]) * (sD[m][s + 1] - sD[m][s]);
        sG[tid] = g;
    }
    __syncthreads();

    // Thread handles columns i and i + NTHREADS (same hw4, bc offset +32).
    const unsigned i   = blockIdx.x * BLOCK + tid;
    const unsigned hw4 = i & (HW4 - 1);
    const unsigned bc  = i >> 12;               // 0..31; second col is bc+32
    const size_t base0 = (size_t)bc * (Tsz * HW4) + hw4;

    float ch0 = 0.f, ch1 = 0.f, ch2 = 0.f, ch3 = 0.f;
    float temp = 0.0f;

    #pragma unroll
    for (int col = 0; col < COLS_PER_THREAD; col++) {
        const size_t base = base0 + (size_t)col * 32 * (Tsz * HW4);
        const float4* __restrict__ px = X + base;
        const float4* __restrict__ py = Y + base;

        float c[Klow][4];               // [dct row][lane]
        #pragma unroll
        for (int n = 0; n < Klow; n++)
            #pragma unroll
            for (int l = 0; l < 4; l++) c[n][l] = 0.0f;

        // 4-timestep staging: 8 independent LDG.128 issued before any use.
        #pragma unroll
        for (int tt = 0; tt < Tsz; tt += 4) {
            float4 a[4], b[4];
            #pragma unroll
            for (int j = 0; j < 4; j++) {
                a[j] = __ldcs(&px[(tt + j) * HW4]);
                b[j] = __ldcs(&py[(tt + j) * HW4]);
            }
            #pragma unroll
            for (int j = 0; j < 4; j++) {
                float d0 = a[j].x - b[j].x;
                float d1 = a[j].y - b[j].y;
                float d2 = a[j].z - b[j].z;
                float d3 = a[j].w - b[j].w;

                ch0 += sqrt_approx(fmaf(d0, d0, EPS2));
                ch1 += sqrt_approx(fmaf(d1, d1, EPS2));
                ch2 += sqrt_approx(fmaf(d2, d2, EPS2));
                ch3 += sqrt_approx(fmaf(d3, d3, EPS2));

                const float4 w = sWT[tt + j];       // broadcast LDS.128
                c[0][0] = fmaf(d0, w.x, c[0][0]);
                c[0][1] = fmaf(d1, w.x, c[0][1]);
                c[0][2] = fmaf(d2, w.x, c[0][2]);
                c[0][3] = fmaf(d3, w.x, c[0][3]);
                c[1][0] = fmaf(d0, w.y, c[1][0]);
                c[1][1] = fmaf(d1, w.y, c[1][1]);
                c[1][2] = fmaf(d2, w.y, c[1][2]);
                c[1][3] = fmaf(d3, w.y, c[1][3]);
                c[2][0] = fmaf(d0, w.z, c[2][0]);
                c[2][1] = fmaf(d1, w.z, c[2][1]);
                c[2][2] = fmaf(d2, w.z, c[2][2]);
                c[2][3] = fmaf(d3, w.z, c[2][3]);
                c[3][0] = fmaf(d0, w.w, c[3][0]);
                c[3][1] = fmaf(d1, w.w, c[3][1]);
                c[3][2] = fmaf(d2, w.w, c[3][2]);
                c[3][3] = fmaf(d3, w.w, c[3][3]);
            }
        }

        // temp += sum over 4 lanes of c^T G c for this column
        #pragma unroll
        for (int l = 0; l < 4; l++) {
            #pragma unroll
            for (int n = 0; n < Klow; n++) {
                float acc = 0.0f;
                #pragma unroll
                for (int m = 0; m < Klow; m++)
                    acc = fmaf(c[m][l], sG[n * Klow + m], acc);
                temp = fmaf(c[n][l], acc, temp);
            }
        }
    }
    float charb = (ch0 + ch1) + (ch2 + ch3);

    // Deterministic block reduction
    red[0][tid] = charb;
    red[1][tid] = temp;
    __syncthreads();
    for (int s = BLOCK / 2; s > 0; s >>= 1) {
        if (tid < s) {
            red[0][tid] += red[0][tid + s];
            red[1][tid] += red[1][tid + s];
        }
        __syncthreads();
    }

    if (tid == 0) {
        g_partials[blockIdx.x]           = red[0][0];
        g_partials[NBLOCKS + blockIdx.x] = red[1][0];
        __threadfence();
        unsigned int ticket = atomicAdd(&g_count, 1u);
        is_last = (ticket == NBLOCKS - 1);
    }
    __syncthreads();

    // Last block: deterministic final reduction in double
    if (is_last) {
        __shared__ double r0[BLOCK];
        __shared__ double r1[BLOCK];
        double s0 = 0.0, s1 = 0.0;
        #pragma unroll 2
        for (int k = tid; k < NBLOCKS; k += BLOCK) {
            s0 += (double)__ldcg(&g_partials[k]);
            s1 += (double)__ldcg(&g_partials[NBLOCKS + k]);
        }
        r0[tid] = s0;
        r1[tid] = s1;
        __syncthreads();
        for (int s = BLOCK / 2; s > 0; s >>= 1) {
            if (tid < s) {
                r0[tid] += r0[tid + s];
                r1[tid] += r1[tid + s];
            }
            __syncthreads();
        }
        if (tid == 0) {
            double L_main = r0[0] / N_MAIN;
            double L_temp = r1[0] / N_TEMP;
            double total  = L_main + TAU * L_temp;
            out[0] = (float)total;
            out[1] = (float)L_main;
            out[2] = (float)L_temp;
            g_count = 0;   // reset for next graph replay
        }
    }
}

extern "C" void kernel_launch(void* const* d_in, const int* in_sizes, int n_in,
                              void* d_out, int out_size)
{
    const float4* X = (const float4*)d_in[0];
    const float4* Y = (const float4*)d_in[1];
    float* out = (float*)d_out;

    loss_fused<<<NBLOCKS, BLOCK>>>(X, Y, out);
}

// round 7
// speedup vs baseline: 1.9729x; 1.9729x over previous
#include <cuda_runtime.h>
#include <math.h>

// Problem constants
#define Bsz   4
#define Csz   16
#define Tsz   32
#define Hsz   128
#define Wsz   128
#define Klow  4
#define TAU   0.1
#define EPS2  1e-12f          // (1e-6)^2

#define HW        (Hsz * Wsz)          // 16384
#define HW4       (HW / 4)             // 4096
#define NCOLS     (Bsz * Csz * HW4)    // 262,144 16B-columns
#define BLOCK     256
#define COLS_PER_BLOCK 64              // 64 columns x 4 t-quarters = 256 threads
#define TQ        (Tsz / 4)            // 8 timesteps per thread
#define NBLOCKS   (NCOLS / COLS_PER_BLOCK)   // 4096

#define N_MAIN  ((double)Bsz * Csz * Tsz * HW)          // 33,554,432
#define N_TEMP  ((double)Bsz * Csz * (Tsz - 1) * HW)    // 32,505,856

__device__ float g_partials[2 * NBLOCKS];
__device__ unsigned int g_count = 0;   // last block resets -> graph-replay safe

// Single-MUFU sqrt (harness has no -use_fast_math; sqrtf would emit a ~15-instr
// correctly-rounded emulation sequence).
__device__ __forceinline__ float sqrt_approx(float x) {
    float r;
    asm("sqrt.approx.f32 %0, %1;" : "=f"(r) : "f"(x));
    return r;
}

__global__ void __launch_bounds__(BLOCK, 4)
loss_fused(const float4* __restrict__ X, const float4* __restrict__ Y,
           float* __restrict__ out)
{
    __shared__ float  sD[Klow][Tsz];       // DCT rows (for building G)
    __shared__ float4 sWT[Tsz];            // per-t packed weights {w0,w1,w2,w3}
    __shared__ float  sG[Klow * Klow];     // G = E E^T
    __shared__ float  sC[3 * 16][COLS_PER_BLOCK];  // quarter partial c's ([k][col]: conflict-free)
    __shared__ float  red[2][BLOCK];
    __shared__ bool   is_last;

    const int tid = threadIdx.x;

    // Build D (4x32): one thread per t; pack into float4 per t.
    if (tid < Tsz) {
        const float s  = sqrtf(2.0f / (float)Tsz);   // setup only
        const float ph = (float)M_PI * (2.0f * tid + 1.0f) / (2.0f * (float)Tsz);
        float w0 = s * 0.7071067811865476f;
        float w1 = s * cosf(ph);
        float w2 = s * cosf(2.0f * ph);
        float w3 = s * cosf(3.0f * ph);
        sD[0][tid] = w0; sD[1][tid] = w1; sD[2][tid] = w2; sD[3][tid] = w3;
        sWT[tid] = make_float4(w0, w1, w2, w3);
    }
    __syncthreads();
    if (tid < Klow * Klow) {
        int n = tid >> 2, m = tid & 3;
        float g = 0.0f;
        #pragma unroll
        for (int s = 0; s < Tsz - 1; s++)
            g += (sD[n][s + 1] - sD[n][s]) * (sD[m][s + 1] - sD[m][s]);
        sG[tid] = g;
    }
    __syncthreads();

    // Thread -> (column, t-quarter). Warp = 32 contiguous columns (coalesced).
    const int c64 = tid & (COLS_PER_BLOCK - 1);     // column within block
    const int q   = tid >> 6;                       // t-quarter 0..3
    const unsigned col = blockIdx.x * COLS_PER_BLOCK + c64;
    const unsigned hw4 = col & (HW4 - 1);
    const unsigned bc  = col >> 12;
    const size_t base  = (size_t)bc * (Tsz * HW4) + hw4;
    const float4* __restrict__ px = X + base + (size_t)(q * TQ) * HW4;
    const float4* __restrict__ py = Y + base + (size_t)(q * TQ) * HW4;

    float ch0 = 0.f, ch1 = 0.f, ch2 = 0.f, ch3 = 0.f;
    float c[Klow][4];                 // [dct row][lane] partials over this quarter
    #pragma unroll
    for (int n = 0; n < Klow; n++)
        #pragma unroll
        for (int l = 0; l < 4; l++) c[n][l] = 0.0f;

    // 8 timesteps: two 4-deep staged batches (8 independent LDG.128 each).
    #pragma unroll
    for (int tt = 0; tt < TQ; tt += 4) {
        float4 a[4], b[4];
        #pragma unroll
        for (int j = 0; j < 4; j++) {
            a[j] = __ldcs(&px[(tt + j) * HW4]);
            b[j] = __ldcs(&py[(tt + j) * HW4]);
        }
        #pragma unroll
        for (int j = 0; j < 4; j++) {
            float d0 = a[j].x - b[j].x;
            float d1 = a[j].y - b[j].y;
            float d2 = a[j].z - b[j].z;
            float d3 = a[j].w - b[j].w;

            ch0 += sqrt_approx(fmaf(d0, d0, EPS2));
            ch1 += sqrt_approx(fmaf(d1, d1, EPS2));
            ch2 += sqrt_approx(fmaf(d2, d2, EPS2));
            ch3 += sqrt_approx(fmaf(d3, d3, EPS2));

            const float4 w = sWT[q * TQ + tt + j];   // broadcast LDS.128
            c[0][0] = fmaf(d0, w.x, c[0][0]);
            c[0][1] = fmaf(d1, w.x, c[0][1]);
            c[0][2] = fmaf(d2, w.x, c[0][2]);
            c[0][3] = fmaf(d3, w.x, c[0][3]);
            c[1][0] = fmaf(d0, w.y, c[1][0]);
            c[1][1] = fmaf(d1, w.y, c[1][1]);
            c[1][2] = fmaf(d2, w.y, c[1][2]);
            c[1][3] = fmaf(d3, w.y, c[1][3]);
            c[2][0] = fmaf(d0, w.z, c[2][0]);
            c[2][1] = fmaf(d1, w.z, c[2][1]);
            c[2][2] = fmaf(d2, w.z, c[2][2]);
            c[2][3] = fmaf(d3, w.z, c[2][3]);
            c[3][0] = fmaf(d0, w.w, c[3][0]);
            c[3][1] = fmaf(d1, w.w, c[3][1]);
            c[3][2] = fmaf(d2, w.w, c[3][2]);
            c[3][3] = fmaf(d3, w.w, c[3][3]);
        }
    }
    float charb = (ch0 + ch1) + (ch2 + ch3);

    // Combine quarter partials: quarters 1..3 publish, quarter 0 sums + quadratic form.
    if (q != 0) {
        #pragma unroll
        for (int n = 0; n < Klow; n++)
            #pragma unroll
            for (int l = 0; l < 4; l++)
                sC[(q - 1) * 16 + n * 4 + l][c64] = c[n][l];
    }
    __syncthreads();

    float temp = 0.0f;
    if (q == 0) {
        #pragma unroll
        for (int n = 0; n < Klow; n++)
            #pragma unroll
            for (int l = 0; l < 4; l++) {
                int k = n * 4 + l;
                c[n][l] += sC[k][c64] + sC[16 + k][c64] + sC[32 + k][c64];
            }
        #pragma unroll
        for (int l = 0; l < 4; l++) {
            #pragma unroll
            for (int n = 0; n < Klow; n++) {
                float acc = 0.0f;
                #pragma unroll
                for (int m = 0; m < Klow; m++)
                    acc = fmaf(c[m][l], sG[n * Klow + m], acc);
                temp = fmaf(c[n][l], acc, temp);
            }
        }
    }

    // Deterministic block reduction (charb from all, temp from quarter-0 threads)
    red[0][tid] = charb;
    red[1][tid] = temp;
    __syncthreads();
    for (int s = BLOCK / 2; s > 0; s >>= 1) {
        if (tid < s) {
            red[0][tid] += red[0][tid + s];
            red[1][tid] += red[1][tid + s];
        }
        __syncthreads();
    }

    if (tid == 0) {
        g_partials[blockIdx.x]           = red[0][0];
        g_partials[NBLOCKS + blockIdx.x] = red[1][0];
        __threadfence();
        unsigned int ticket = atomicAdd(&g_count, 1u);
        is_last = (ticket == NBLOCKS - 1);
    }
    __syncthreads();

    // Last block: deterministic final reduction in double
    if (is_last) {
        __shared__ double r0[BLOCK];
        __shared__ double r1[BLOCK];
        double s0 = 0.0, s1 = 0.0;
        #pragma unroll 4
        for (int k = tid; k < NBLOCKS; k += BLOCK) {
            s0 += (double)__ldcg(&g_partials[k]);
            s1 += (double)__ldcg(&g_partials[NBLOCKS + k]);
        }
        r0[tid] = s0;
        r1[tid] = s1;
        __syncthreads();
        for (int s = BLOCK / 2; s > 0; s >>= 1) {
            if (tid < s) {
                r0[tid] += r0[tid + s];
                r1[tid] += r1[tid + s];
            }
            __syncthreads();
        }
        if (tid == 0) {
            double L_main = r0[0] / N_MAIN;
            double L_temp = r1[0] / N_TEMP;
            double total  = L_main + TAU * L_temp;
            out[0] = (float)total;
            out[1] = (float)L_main;
            out[2] = (float)L_temp;
            g_count = 0;   // reset for next graph replay
        }
    }
}

extern "C" void kernel_launch(void* const* d_in, const int* in_sizes, int n_in,
                              void* d_out, int out_size)
{
    const float4* X = (const float4*)d_in[0];
    const float4* Y = (const float4*)d_in[1];
    float* out = (float*)d_out;

    loss_fused<<<NBLOCKS, BLOCK>>>(X, Y, out);
}

// round 8
// speedup vs baseline: 2.4609x; 1.2474x over previous
#include <cuda_runtime.h>
#include <math.h>

// Problem constants
#define Bsz   4
#define Csz   16
#define Tsz   32
#define Hsz   128
#define Wsz   128
#define Klow  4
#define TAU   0.1
#define EPS2  1e-12f          // (1e-6)^2

#define HW        (Hsz * Wsz)          // 16384
#define HW4       (HW / 4)             // 4096
#define NCOLS     (Bsz * Csz * HW4)    // 262,144 16B-columns
#define BLOCK     256
#define NBLOCKS   512                  // all co-resident (<= 592 cap) -> zero wave tail
#define NTHREADS  (NBLOCKS * BLOCK)    // 131,072 -> 2 columns per thread
#define COLS_PER_THREAD 2

#define N_MAIN  ((double)Bsz * Csz * Tsz * HW)          // 33,554,432
#define N_TEMP  ((double)Bsz * Csz * (Tsz - 1) * HW)    // 32,505,856

__device__ float g_partials[2 * NBLOCKS];
__device__ unsigned int g_count = 0;   // last block resets -> graph-replay safe

// Single-MUFU sqrt (harness has no -use_fast_math; sqrtf would emit a ~15-instr
// correctly-rounded emulation sequence).
__device__ __forceinline__ float sqrt_approx(float x) {
    float r;
    asm("sqrt.approx.f32 %0, %1;" : "=f"(r) : "f"(x));
    return r;
}

__global__ void __launch_bounds__(BLOCK)
loss_fused(const float4* __restrict__ X, const float4* __restrict__ Y,
           float* __restrict__ out)
{
    __shared__ float  sD[Klow][Tsz];    // DCT rows (for building G)
    __shared__ float4 sWT[Tsz];         // per-t packed weights {w0,w1,w2,w3}
    __shared__ float  sG[Klow * Klow];  // G = E E^T
    __shared__ float  red[2][BLOCK];
    __shared__ bool   is_last;

    const int tid = threadIdx.x;

    // Build D (4x32): one thread per t; pack into float4 per t.
    if (tid < Tsz) {
        const float s  = sqrtf(2.0f / (float)Tsz);   // setup only
        const float ph = (float)M_PI * (2.0f * tid + 1.0f) / (2.0f * (float)Tsz);
        float w0 = s * 0.7071067811865476f;
        float w1 = s * cosf(ph);
        float w2 = s * cosf(2.0f * ph);
        float w3 = s * cosf(3.0f * ph);
        sD[0][tid] = w0; sD[1][tid] = w1; sD[2][tid] = w2; sD[3][tid] = w3;
        sWT[tid] = make_float4(w0, w1, w2, w3);
    }
    __syncthreads();
    if (tid < Klow * Klow) {
        int n = tid >> 2, m = tid & 3;
        float g = 0.0f;
        #pragma unroll
        for (int s = 0; s < Tsz - 1; s++)
            g += (sD[n][s + 1] - sD[n][s]) * (sD[m][s + 1] - sD[m][s]);
        sG[tid] = g;
    }
    __syncthreads();

    // Thread handles columns i and i + NTHREADS (same hw4, bc offset +32).
    const unsigned i   = blockIdx.x * BLOCK + tid;
    const unsigned hw4 = i & (HW4 - 1);
    const unsigned bc  = i >> 12;               // 0..31; second col is bc+32
    const size_t base0 = (size_t)bc * (Tsz * HW4) + hw4;

    float ch0 = 0.f, ch1 = 0.f, ch2 = 0.f, ch3 = 0.f;
    float temp = 0.0f;

    // CRITICAL: unroll 1 — unrolling this loop lets ptxas merge both columns'
    // 128 loads into one straight line and spill (R6: +229 MB DRAM traffic).
    #pragma unroll 1
    for (int colit = 0; colit < COLS_PER_THREAD; colit++) {
        const size_t base = base0 + (size_t)colit * 32 * (Tsz * HW4);
        const float4* __restrict__ px = X + base;
        const float4* __restrict__ py = Y + base;

        float c[Klow][4];               // [dct row][lane]
        #pragma unroll
        for (int n = 0; n < Klow; n++)
            #pragma unroll
            for (int l = 0; l < 4; l++) c[n][l] = 0.0f;

        // 4-timestep staging: 8 independent LDG.128 issued before any use.
        #pragma unroll
        for (int tt = 0; tt < Tsz; tt += 4) {
            float4 a[4], b[4];
            #pragma unroll
            for (int j = 0; j < 4; j++) {
                a[j] = __ldcs(&px[(tt + j) * HW4]);
                b[j] = __ldcs(&py[(tt + j) * HW4]);
            }
            #pragma unroll
            for (int j = 0; j < 4; j++) {
                float d0 = a[j].x - b[j].x;
                float d1 = a[j].y - b[j].y;
                float d2 = a[j].z - b[j].z;
                float d3 = a[j].w - b[j].w;

                ch0 += sqrt_approx(fmaf(d0, d0, EPS2));
                ch1 += sqrt_approx(fmaf(d1, d1, EPS2));
                ch2 += sqrt_approx(fmaf(d2, d2, EPS2));
                ch3 += sqrt_approx(fmaf(d3, d3, EPS2));

                const float4 w = sWT[tt + j];       // broadcast LDS.128
                c[0][0] = fmaf(d0, w.x, c[0][0]);
                c[0][1] = fmaf(d1, w.x, c[0][1]);
                c[0][2] = fmaf(d2, w.x, c[0][2]);
                c[0][3] = fmaf(d3, w.x, c[0][3]);
                c[1][0] = fmaf(d0, w.y, c[1][0]);
                c[1][1] = fmaf(d1, w.y, c[1][1]);
                c[1][2] = fmaf(d2, w.y, c[1][2]);
                c[1][3] = fmaf(d3, w.y, c[1][3]);
                c[2][0] = fmaf(d0, w.z, c[2][0]);
                c[2][1] = fmaf(d1, w.z, c[2][1]);
                c[2][2] = fmaf(d2, w.z, c[2][2]);
                c[2][3] = fmaf(d3, w.z, c[2][3]);
                c[3][0] = fmaf(d0, w.w, c[3][0]);
                c[3][1] = fmaf(d1, w.w, c[3][1]);
                c[3][2] = fmaf(d2, w.w, c[3][2]);
                c[3][3] = fmaf(d3, w.w, c[3][3]);
            }
        }

        // temp += sum over 4 lanes of c^T G c for this column
        #pragma unroll
        for (int l = 0; l < 4; l++) {
            #pragma unroll
            for (int n = 0; n < Klow; n++) {
                float acc = 0.0f;
                #pragma unroll
                for (int m = 0; m < Klow; m++)
                    acc = fmaf(c[m][l], sG[n * Klow + m], acc);
                temp = fmaf(c[n][l], acc, temp);
            }
        }
    }
    float charb = (ch0 + ch1) + (ch2 + ch3);

    // Deterministic block reduction
    red[0][tid] = charb;
    red[1][tid] = temp;
    __syncthreads();
    for (int s = BLOCK / 2; s > 0; s >>= 1) {
        if (tid < s) {
            red[0][tid] += red[0][tid + s];
            red[1][tid] += red[1][tid + s];
        }
        __syncthreads();
    }

    if (tid == 0) {
        g_partials[blockIdx.x]           = red[0][0];
        g_partials[NBLOCKS + blockIdx.x] = red[1][0];
        __threadfence();
        unsigned int ticket = atomicAdd(&g_count, 1u);
        is_last = (ticket == NBLOCKS - 1);
    }
    __syncthreads();

    // Last block: deterministic final reduction in double
    if (is_last) {
        __shared__ double r0[BLOCK];
        __shared__ double r1[BLOCK];
        double s0 = 0.0, s1 = 0.0;
        #pragma unroll 2
        for (int k = tid; k < NBLOCKS; k += BLOCK) {
            s0 += (double)__ldcg(&g_partials[k]);
            s1 += (double)__ldcg(&g_partials[NBLOCKS + k]);
        }
        r0[tid] = s0;
        r1[tid] = s1;
        __syncthreads();
        for (int s = BLOCK / 2; s > 0; s >>= 1) {
            if (tid < s) {
                r0[tid] += r0[tid + s];
                r1[tid] += r1[tid + s];
            }
            __syncthreads();
        }
        if (tid == 0) {
            double L_main = r0[0] / N_MAIN;
            double L_temp = r1[0] / N_TEMP;
            double total  = L_main + TAU * L_temp;
            out[0] = (float)total;
            out[1] = (float)L_main;
            out[2] = (float)L_temp;
            g_count = 0;   // reset for next graph replay
        }
    }
}

extern "C" void kernel_launch(void* const* d_in, const int* in_sizes, int n_in,
                              void* d_out, int out_size)
{
    const float4* X = (const float4*)d_in[0];
    const float4* Y = (const float4*)d_in[1];
    float* out = (float*)d_out;

    loss_fused<<<NBLOCKS, BLOCK>>>(X, Y, out);
}